// round 8
// baseline (speedup 1.0000x reference)
#include <cuda_runtime.h>
#include <cuda_bf16.h>
#include <cstdint>

#define M_TOK 8192
#define N_OUT 4096
#define K_IN  4096
#define K3    (3 * K_IN)          // 12288 int8: [X1 | X1 | X2] x [W1 | W2 | W1]

#define BM 128
#define BN 128
#define BK 128                    // int8 elements per chunk (=128 bytes/row)
#define NCHUNK (K3 / BK)          // 96
#define SEC_BOUND 32              // chunks 0..31 = X1*W1 (scale S); rest scale S/256
#define NSTAGE 4
#define A_BYTES (BM * BK)         // 16384
#define B_BYTES (BN * BK)         // 16384
#define STAGE_BYTES (A_BYTES + B_BYTES)    // 32768
#define SMEM_TOTAL (NSTAGE * STAGE_BYTES)  // 131072

#define GRID_M (M_TOK / BM)       // 64
#define GRID_N (N_OUT / BN)       // 32
#define GROUP_M 8

// -------------------- static device scratch --------------------
__device__ int8_t g_ax[(size_t)M_TOK * K3];     // 100 MB
__device__ int8_t g_bw[(size_t)N_OUT * K3];     //  50 MB
__device__ float  g_wf[(size_t)N_OUT * K_IN];   //  67 MB fused W
__device__ unsigned int g_maxx, g_maxw;

// -------------------- helpers --------------------
static __device__ __forceinline__ uint32_t s2u(const void* p) {
    uint32_t a;
    asm("{ .reg .u64 t; cvta.to.shared.u64 t, %1; cvt.u32.u64 %0, t; }"
        : "=r"(a) : "l"(p));
    return a;
}
#define SWZ(o) ((o) ^ (((o) >> 3) & 0x70))

static __device__ __forceinline__ void cp16(uint32_t dst, const void* src) {
    asm volatile("cp.async.cg.shared.global [%0], [%1], 16;" :: "r"(dst), "l"(src));
}
static __device__ __forceinline__ void cp_commit() {
    asm volatile("cp.async.commit_group;" ::: "memory");
}

static __device__ __forceinline__ void ldmx4(uint32_t* r, uint32_t addr) {
    asm volatile("ldmatrix.sync.aligned.m8n8.x4.shared.b16 {%0,%1,%2,%3}, [%4];"
                 : "=r"(r[0]), "=r"(r[1]), "=r"(r[2]), "=r"(r[3]) : "r"(addr));
}
// s8 IMMA m16n8k32: byte-layout of fragments matches b16 m16n8k16, so the same
// ldmatrix addressing works with k measured in bytes.
static __device__ __forceinline__ void imma16832(int* c, const uint32_t* a,
                                                 uint32_t b0, uint32_t b1) {
    asm volatile(
        "mma.sync.aligned.m16n8k32.row.col.s32.s8.s8.s32 "
        "{%0,%1,%2,%3}, {%4,%5,%6,%7}, {%8,%9}, {%0,%1,%2,%3};"
        : "+r"(c[0]), "+r"(c[1]), "+r"(c[2]), "+r"(c[3])
        : "r"(a[0]), "r"(a[1]), "r"(a[2]), "r"(a[3]), "r"(b0), "r"(b1));
}

static __device__ __forceinline__ void quant2(float x, float inv_s, int8_t& q1, int8_t& q2) {
    float v = x * inv_s;                       // in [-127, 127]
    int i1 = __float2int_rn(v);
    int i2 = __float2int_rn((v - (float)i1) * 256.0f);
    i2 = min(127, max(-128, i2));
    q1 = (int8_t)i1; q2 = (int8_t)i2;
}

// block-level max-abs reduce + one atomicMax
static __device__ __forceinline__ void block_max_atomic(float m, unsigned int* dst) {
    #pragma unroll
    for (int off = 16; off; off >>= 1)
        m = fmaxf(m, __shfl_xor_sync(0xffffffffu, m, off));
    __shared__ float wm[32];
    const int lane = threadIdx.x & 31, wid = threadIdx.x >> 5;
    if (lane == 0) wm[wid] = m;
    __syncthreads();
    if (wid == 0) {
        m = (lane < (int)(blockDim.x >> 5)) ? wm[lane] : 0.f;
        #pragma unroll
        for (int off = 16; off; off >>= 1)
            m = fmaxf(m, __shfl_xor_sync(0xffffffffu, m, off));
        if (lane == 0) atomicMax(dst, __float_as_uint(m));
    }
}

// -------------------- prepass 0: reset scales --------------------
__global__ void init_scales() { g_maxx = 0u; g_maxw = 0u; }

// -------------------- prepass 1: max|x| --------------------
__global__ __launch_bounds__(256) void max_x(const float* __restrict__ x) {
    const size_t stride = (size_t)gridDim.x * 256 * 4;
    size_t i = ((size_t)blockIdx.x * 256 + threadIdx.x) * 4;
    float m = 0.f;
    for (; i < (size_t)M_TOK * K_IN; i += stride) {
        float4 v = *(const float4*)(x + i);
        m = fmaxf(m, fmaxf(fmaxf(fabsf(v.x), fabsf(v.y)),
                           fmaxf(fabsf(v.z), fabsf(v.w))));
    }
    block_max_atomic(m, &g_maxx);
}

// ------------- prepass 2: Wf = W + s*B@A -> g_wf, track max ----------------
__global__ __launch_bounds__(256) void fuse_w(
    const float* __restrict__ W, const float* __restrict__ B,
    const float* __restrict__ A, const float* __restrict__ sp)
{
    size_t idx4 = (size_t)blockIdx.x * 256 + threadIdx.x;
    int row = (int)(idx4 >> 10);
    int col = (int)(idx4 & 1023) * 4;
    float s = *sp;

    float4 w = *(const float4*)(W + (size_t)row * K_IN + col);
    float4 acc = make_float4(0.f, 0.f, 0.f, 0.f);
    const float* brow = B + (size_t)row * 16;
    #pragma unroll
    for (int r = 0; r < 16; r++) {
        float b = brow[r];
        float4 a = *(const float4*)(A + (size_t)r * K_IN + col);
        acc.x += b * a.x; acc.y += b * a.y; acc.z += b * a.z; acc.w += b * a.w;
    }
    w.x += s * acc.x; w.y += s * acc.y; w.z += s * acc.z; w.w += s * acc.w;
    *(float4*)(g_wf + (size_t)row * K_IN + col) = w;

    float m = fmaxf(fmaxf(fabsf(w.x), fabsf(w.y)), fmaxf(fabsf(w.z), fabsf(w.w)));
    block_max_atomic(m, &g_maxw);
}

// ---------- prepass 3: quantize x -> g_ax rows [X1 | X1 | X2] ----------
__global__ __launch_bounds__(256) void pack_x(const float* __restrict__ x) {
    size_t idx4 = (size_t)blockIdx.x * 256 + threadIdx.x;
    int row = (int)(idx4 >> 10);
    int col = (int)(idx4 & 1023) * 4;
    const float inv_sx = 127.0f / fmaxf(__uint_as_float(g_maxx), 1e-30f);

    float4 v = *(const float4*)(x + (size_t)row * K_IN + col);
    char4 q1, q2;
    quant2(v.x, inv_sx, (int8_t&)q1.x, (int8_t&)q2.x);
    quant2(v.y, inv_sx, (int8_t&)q1.y, (int8_t&)q2.y);
    quant2(v.z, inv_sx, (int8_t&)q1.z, (int8_t&)q2.z);
    quant2(v.w, inv_sx, (int8_t&)q1.w, (int8_t&)q2.w);

    int8_t* base = g_ax + (size_t)row * K3 + col;
    *(char4*)(base)            = q1;
    *(char4*)(base + K_IN)     = q1;
    *(char4*)(base + 2 * K_IN) = q2;
}

// ---------- prepass 4: quantize Wf -> g_bw rows [W1 | W2 | W1] ----------
__global__ __launch_bounds__(256) void pack_w() {
    size_t idx4 = (size_t)blockIdx.x * 256 + threadIdx.x;
    int row = (int)(idx4 >> 10);
    int col = (int)(idx4 & 1023) * 4;
    const float inv_sw = 127.0f / fmaxf(__uint_as_float(g_maxw), 1e-30f);

    float4 v = *(const float4*)(g_wf + (size_t)row * K_IN + col);
    char4 q1, q2;
    quant2(v.x, inv_sw, (int8_t&)q1.x, (int8_t&)q2.x);
    quant2(v.y, inv_sw, (int8_t&)q1.y, (int8_t&)q2.y);
    quant2(v.z, inv_sw, (int8_t&)q1.z, (int8_t&)q2.z);
    quant2(v.w, inv_sw, (int8_t&)q1.w, (int8_t&)q2.w);

    int8_t* base = g_bw + (size_t)row * K3 + col;
    *(char4*)(base)            = q1;
    *(char4*)(base + K_IN)     = q2;
    *(char4*)(base + 2 * K_IN) = q1;
}

// -------------------- main GEMM: int8 IMMA, split-scale --------------------
__global__ __launch_bounds__(256, 1) void lora_imma_gemm(
    const float* __restrict__ bias, float* __restrict__ out)
{
    extern __shared__ __align__(1024) char smem[];
    const uint32_t sb = s2u(smem);
    const int tid  = threadIdx.x;
    const int lane = tid & 31;
    const int wid  = tid >> 5;
    const int warp_m = wid & 1;       // 2 warps in M -> 64 rows each
    const int warp_n = wid >> 1;      // 4 warps in N -> 32 cols each

    const int bid   = blockIdx.x;
    const int group = bid / (GROUP_M * GRID_N);
    const int inner = bid % (GROUP_M * GRID_N);
    const int bm    = (group * GROUP_M + (inner % GROUP_M)) * BM;
    const int bn    = (inner / GROUP_M) * BN;

    const float S = (__uint_as_float(g_maxx) / 127.0f) *
                    (__uint_as_float(g_maxw) / 127.0f);

    const int8_t* Ag = g_ax + (size_t)bm * K3;
    const int8_t* Bg = g_bw + (size_t)bn * K3;

    const int lrow = lane & 15;
    const int lkb  = (lane >> 4) * 16;

    int   c[4][4][4];
    float f[4][4][4];
    #pragma unroll
    for (int i = 0; i < 4; i++)
        #pragma unroll
        for (int j = 0; j < 4; j++)
            #pragma unroll
            for (int q = 0; q < 4; q++) { c[i][j][q] = 0; f[i][j][q] = 0.f; }

    auto load_stage = [&](int ch, int st) {
        const uint32_t ab = sb + st * STAGE_BYTES;
        const uint32_t bb = ab + A_BYTES;
        const int k0 = ch * BK;
        #pragma unroll
        for (int i = 0; i < 4; i++) {       // A: 1024 granules of 16B
            int G = tid + i * 256;
            int r = G >> 3, g = G & 7;
            cp16(ab + SWZ((uint32_t)(r * 128 + g * 16)),
                 Ag + (size_t)r * K3 + k0 + g * 16);
        }
        #pragma unroll
        for (int i = 0; i < 4; i++) {       // B: 1024 granules
            int G = tid + i * 256;
            int r = G >> 3, g = G & 7;
            cp16(bb + SWZ((uint32_t)(r * 128 + g * 16)),
                 Bg + (size_t)r * K3 + k0 + g * 16);
        }
        cp_commit();
    };

    #pragma unroll
    for (int s = 0; s < NSTAGE - 1; s++) load_stage(s, s);

    for (int ch = 0; ch < NCHUNK; ch++) {
        if (ch == SEC_BOUND) {   // section 0 done: bank X1*W1 at scale S, reset ints
            #pragma unroll
            for (int i = 0; i < 4; i++)
                #pragma unroll
                for (int j = 0; j < 4; j++)
                    #pragma unroll
                    for (int q = 0; q < 4; q++) {
                        f[i][j][q] = S * (float)c[i][j][q];
                        c[i][j][q] = 0;
                    }
        }

        asm volatile("cp.async.wait_group 2;" ::: "memory");
        __syncthreads();

        if (ch + NSTAGE - 1 < NCHUNK) load_stage(ch + NSTAGE - 1, (ch + NSTAGE - 1) & 3);
        else cp_commit();   // keep group accounting balanced

        const int st = ch & 3;
        const uint32_t ab = sb + st * STAGE_BYTES;
        const uint32_t bb = ab + A_BYTES;

        #pragma unroll
        for (int ks = 0; ks < 4; ks++) {    // 4 x k32 per 128-byte chunk
            uint32_t ra[4][4], rb[2][4];
            #pragma unroll
            for (int mf = 0; mf < 4; mf++)
                ldmx4(ra[mf], ab + SWZ((uint32_t)((warp_m * 64 + mf * 16 + lrow) * 128
                                                  + ks * 32 + lkb)));
            #pragma unroll
            for (int nf2 = 0; nf2 < 2; nf2++)
                ldmx4(rb[nf2], bb + SWZ((uint32_t)((warp_n * 32 + nf2 * 16 + lrow) * 128
                                                   + ks * 32 + lkb)));
            #pragma unroll
            for (int mf = 0; mf < 4; mf++)
                #pragma unroll
                for (int nf = 0; nf < 4; nf++)
                    imma16832(c[mf][nf], ra[mf],
                              rb[nf >> 1][nf & 1], rb[nf >> 1][(nf & 1) + 2]);
        }
    }

    // -------- epilogue: f + (S/256)*c + bias -> gmem --------
    const float S2 = S * (1.0f / 256.0f);
    const int tq = lane >> 2, t4 = lane & 3;
    float2 bv[4];
    #pragma unroll
    for (int nf = 0; nf < 4; nf++)
        bv[nf] = *(const float2*)(bias + bn + warp_n * 32 + nf * 8 + t4 * 2);

    #pragma unroll
    for (int mf = 0; mf < 4; mf++) {
        const int r0 = bm + warp_m * 64 + mf * 16 + tq;
        float* o0 = out + (size_t)r0 * N_OUT + bn + warp_n * 32;
        float* o1 = o0 + 8 * N_OUT;
        #pragma unroll
        for (int nf = 0; nf < 4; nf++) {
            const int colo = nf * 8 + t4 * 2;
            *(float2*)(o0 + colo) = make_float2(
                f[mf][nf][0] + S2 * (float)c[mf][nf][0] + bv[nf].x,
                f[mf][nf][1] + S2 * (float)c[mf][nf][1] + bv[nf].y);
            *(float2*)(o1 + colo) = make_float2(
                f[mf][nf][2] + S2 * (float)c[mf][nf][2] + bv[nf].x,
                f[mf][nf][3] + S2 * (float)c[mf][nf][3] + bv[nf].y);
        }
    }
}

// -------------------- launch --------------------
extern "C" void kernel_launch(void* const* d_in, const int* in_sizes, int n_in,
                              void* d_out, int out_size)
{
    (void)in_sizes; (void)n_in; (void)out_size;
    const float* x     = (const float*)d_in[0];
    const float* W     = (const float*)d_in[1];
    const float* bias  = (const float*)d_in[2];
    const float* loraB = (const float*)d_in[3];
    const float* loraA = (const float*)d_in[4];
    const float* scale = (const float*)d_in[5];
    float* out = (float*)d_out;

    init_scales<<<1, 32>>>();
    max_x<<<4096, 256>>>(x);
    fuse_w<<<(int)((size_t)N_OUT * K_IN / 1024), 256>>>(W, loraB, loraA, scale);
    pack_x<<<(int)((size_t)M_TOK * K_IN / 1024), 256>>>(x);
    pack_w<<<(int)((size_t)N_OUT * K_IN / 1024), 256>>>();

    cudaFuncSetAttribute(lora_imma_gemm,
                         cudaFuncAttributeMaxDynamicSharedMemorySize, SMEM_TOTAL);
    lora_imma_gemm<<<GRID_M * GRID_N, 256, SMEM_TOTAL>>>(bias, out);
}

// round 9
// speedup vs baseline: 2.6448x; 2.6448x over previous
#include <cuda_runtime.h>
#include <cuda_bf16.h>
#include <cstdint>

#define M_TOK 8192
#define N_OUT 4096
#define K_IN  4096
#define K3    (3 * K_IN)          // 12288: [hi | hi | lo] x [hi | lo | hi]

#define BM 128
#define BN 128
#define BK 64
#define NCHUNK (K3 / BK)          // 192
#define NSTAGE 3
#define A_BYTES (BM * BK * 2)     // 16384
#define B_BYTES (BN * BK * 2)     // 16384
#define STAGE_BYTES (A_BYTES + B_BYTES)        // 32768
#define SMEM_TOTAL (NSTAGE * STAGE_BYTES)      // 98304 -> 2 CTAs/SM

#define NTHREADS 128              // 4 warps, each owns a 64x64 warp tile

#define GRID_M (M_TOK / BM)       // 64
#define GRID_N (N_OUT / BN)       // 32
#define GROUP_M 8

// -------------------- static device scratch (288 MB) --------------------
__device__ __nv_bfloat16 g_ax[(size_t)M_TOK * K3];
__device__ __nv_bfloat16 g_bw[(size_t)N_OUT * K3];

// -------------------- helpers --------------------
static __device__ __forceinline__ uint32_t s2u(const void* p) {
    uint32_t a;
    asm("{ .reg .u64 t; cvta.to.shared.u64 t, %1; cvt.u32.u64 %0, t; }"
        : "=r"(a) : "l"(p));
    return a;
}
#define SWZ(o) ((o) ^ (((o) >> 3) & 0x70))

static __device__ __forceinline__ void cp16(uint32_t dst, const void* src) {
    asm volatile("cp.async.cg.shared.global [%0], [%1], 16;" :: "r"(dst), "l"(src));
}
static __device__ __forceinline__ void cp_commit() {
    asm volatile("cp.async.commit_group;" ::: "memory");
}

static __device__ __forceinline__ void ldmx4(uint32_t* r, uint32_t addr) {
    asm volatile("ldmatrix.sync.aligned.m8n8.x4.shared.b16 {%0,%1,%2,%3}, [%4];"
                 : "=r"(r[0]), "=r"(r[1]), "=r"(r[2]), "=r"(r[3]) : "r"(addr));
}
static __device__ __forceinline__ void mma16816(float* c, const uint32_t* a,
                                                uint32_t b0, uint32_t b1) {
    asm volatile(
        "mma.sync.aligned.m16n8k16.row.col.f32.bf16.bf16.f32 "
        "{%0,%1,%2,%3}, {%4,%5,%6,%7}, {%8,%9}, {%0,%1,%2,%3};"
        : "+f"(c[0]), "+f"(c[1]), "+f"(c[2]), "+f"(c[3])
        : "r"(a[0]), "r"(a[1]), "r"(a[2]), "r"(a[3]), "r"(b0), "r"(b1));
}

static __device__ __forceinline__ void split1(float v, unsigned short& h, unsigned short& l) {
    __nv_bfloat16 hb = __float2bfloat16(v);
    float r = v - __bfloat162float(hb);
    __nv_bfloat16 lb = __float2bfloat16(r);
    h = __bfloat16_as_ushort(hb);
    l = __bfloat16_as_ushort(lb);
}

// ---------- prepass 1: x -> g_ax rows [xh | xh | xl] ----------
__global__ __launch_bounds__(256) void pack_x(const float* __restrict__ x) {
    size_t idx4 = (size_t)blockIdx.x * 256 + threadIdx.x;
    int row = (int)(idx4 >> 10);
    int col = (int)(idx4 & 1023) * 4;
    float4 v = *(const float4*)(x + (size_t)row * K_IN + col);
    ushort4 h, l;
    split1(v.x, h.x, l.x); split1(v.y, h.y, l.y);
    split1(v.z, h.z, l.z); split1(v.w, h.w, l.w);
    unsigned short* base = (unsigned short*)g_ax + (size_t)row * K3 + col;
    *(ushort4*)(base)            = h;
    *(ushort4*)(base + K_IN)     = h;
    *(ushort4*)(base + 2 * K_IN) = l;
}

// ---------- prepass 2: Wf = W + s*B@A -> g_bw rows [wh | wl | wh] ----------
__global__ __launch_bounds__(256) void pack_w(
    const float* __restrict__ W, const float* __restrict__ B,
    const float* __restrict__ A, const float* __restrict__ sp)
{
    size_t idx4 = (size_t)blockIdx.x * 256 + threadIdx.x;
    int row = (int)(idx4 >> 10);
    int col = (int)(idx4 & 1023) * 4;
    float s = *sp;

    float4 w = *(const float4*)(W + (size_t)row * K_IN + col);
    float4 acc = make_float4(0.f, 0.f, 0.f, 0.f);
    const float* brow = B + (size_t)row * 16;
    #pragma unroll
    for (int r = 0; r < 16; r++) {
        float b = brow[r];
        float4 a = *(const float4*)(A + (size_t)r * K_IN + col);
        acc.x += b * a.x; acc.y += b * a.y; acc.z += b * a.z; acc.w += b * a.w;
    }
    w.x += s * acc.x; w.y += s * acc.y; w.z += s * acc.z; w.w += s * acc.w;

    ushort4 h, l;
    split1(w.x, h.x, l.x); split1(w.y, h.y, l.y);
    split1(w.z, h.z, l.z); split1(w.w, h.w, l.w);
    unsigned short* base = (unsigned short*)g_bw + (size_t)row * K3 + col;
    *(ushort4*)(base)            = h;
    *(ushort4*)(base + K_IN)     = l;
    *(ushort4*)(base + 2 * K_IN) = h;
}

// -------------------- main GEMM: out = A' @ B'^T + bias --------------------
__global__ __launch_bounds__(NTHREADS, 2) void lora_mma_gemm(
    const float* __restrict__ bias, float* __restrict__ out)
{
    extern __shared__ __align__(1024) char smem[];
    const uint32_t sb = s2u(smem);
    const int tid  = threadIdx.x;
    const int lane = tid & 31;
    const int wid  = tid >> 5;
    const int warp_m = wid & 1;       // 2 warps in M -> 64 rows each
    const int warp_n = wid >> 1;      // 2 warps in N -> 64 cols each

    const int bid   = blockIdx.x;
    const int group = bid / (GROUP_M * GRID_N);
    const int inner = bid % (GROUP_M * GRID_N);
    const int bm    = (group * GROUP_M + (inner % GROUP_M)) * BM;
    const int bn    = (inner / GROUP_M) * BN;

    const __nv_bfloat16* Ag = g_ax + (size_t)bm * K3;
    const __nv_bfloat16* Bg = g_bw + (size_t)bn * K3;

    const int lrow = lane & 15;
    const int lkb  = (lane >> 4) * 16;

    float c[4][8][4];
    #pragma unroll
    for (int i = 0; i < 4; i++)
        #pragma unroll
        for (int j = 0; j < 8; j++)
            #pragma unroll
            for (int q = 0; q < 4; q++) c[i][j][q] = 0.f;

    auto load_stage = [&](int ch, int st) {
        const uint32_t ab = sb + st * STAGE_BYTES;
        const uint32_t bb = ab + A_BYTES;
        const int k0 = ch * BK;
        #pragma unroll
        for (int i = 0; i < 8; i++) {       // A: 1024 granules of 16B
            int G = tid + i * NTHREADS;
            int r = G >> 3, g = G & 7;
            cp16(ab + SWZ((uint32_t)(r * 128 + g * 16)),
                 Ag + (size_t)r * K3 + k0 + g * 8);
        }
        #pragma unroll
        for (int i = 0; i < 8; i++) {       // B: 1024 granules
            int G = tid + i * NTHREADS;
            int r = G >> 3, g = G & 7;
            cp16(bb + SWZ((uint32_t)(r * 128 + g * 16)),
                 Bg + (size_t)r * K3 + k0 + g * 8);
        }
        cp_commit();
    };

    #pragma unroll
    for (int s = 0; s < NSTAGE - 1; s++) load_stage(s, s);

    for (int ch = 0; ch < NCHUNK; ch++) {
        asm volatile("cp.async.wait_group 1;" ::: "memory");
        __syncthreads();

        // load stage ch+2 into slot (ch+2)%3 — that slot held ch-1, which was
        // fully consumed in the previous iteration, before the barrier above
        if (ch + NSTAGE - 1 < NCHUNK) {
            const int nc = ch + NSTAGE - 1;
            load_stage(nc, nc % NSTAGE);
        } else cp_commit();   // keep group accounting balanced

        const int st = ch % NSTAGE;
        const uint32_t ab = sb + st * STAGE_BYTES;
        const uint32_t bb = ab + A_BYTES;

        #pragma unroll
        for (int ks = 0; ks < 4; ks++) {
            uint32_t ra[4][4], rb[4][4];
            #pragma unroll
            for (int mf = 0; mf < 4; mf++)
                ldmx4(ra[mf], ab + SWZ((uint32_t)((warp_m * 64 + mf * 16 + lrow) * 128
                                                  + ks * 32 + lkb)));
            #pragma unroll
            for (int j = 0; j < 4; j++)
                ldmx4(rb[j], bb + SWZ((uint32_t)((warp_n * 64 + j * 16 + lrow) * 128
                                                 + ks * 32 + lkb)));
            #pragma unroll
            for (int mf = 0; mf < 4; mf++)
                #pragma unroll
                for (int nf = 0; nf < 8; nf++)
                    mma16816(c[mf][nf], ra[mf],
                             rb[nf >> 1][nf & 1], rb[nf >> 1][(nf & 1) + 2]);
        }
    }

    // -------- epilogue: regs + bias -> gmem --------
    const int tq = lane >> 2, t4 = lane & 3;
    float2 bv[8];
    #pragma unroll
    for (int nf = 0; nf < 8; nf++)
        bv[nf] = *(const float2*)(bias + bn + warp_n * 64 + nf * 8 + t4 * 2);

    #pragma unroll
    for (int mf = 0; mf < 4; mf++) {
        const int r0 = bm + warp_m * 64 + mf * 16 + tq;
        float* o0 = out + (size_t)r0 * N_OUT + bn + warp_n * 64;
        float* o1 = o0 + 8 * N_OUT;
        #pragma unroll
        for (int nf = 0; nf < 8; nf++) {
            const int colo = nf * 8 + t4 * 2;
            *(float2*)(o0 + colo) = make_float2(c[mf][nf][0] + bv[nf].x,
                                                c[mf][nf][1] + bv[nf].y);
            *(float2*)(o1 + colo) = make_float2(c[mf][nf][2] + bv[nf].x,
                                                c[mf][nf][3] + bv[nf].y);
        }
    }
}

// -------------------- launch --------------------
extern "C" void kernel_launch(void* const* d_in, const int* in_sizes, int n_in,
                              void* d_out, int out_size)
{
    (void)in_sizes; (void)n_in; (void)out_size;
    const float* x     = (const float*)d_in[0];
    const float* W     = (const float*)d_in[1];
    const float* bias  = (const float*)d_in[2];
    const float* loraB = (const float*)d_in[3];
    const float* loraA = (const float*)d_in[4];
    const float* scale = (const float*)d_in[5];
    float* out = (float*)d_out;

    pack_x<<<(int)((size_t)M_TOK * K_IN / 1024), 256>>>(x);
    pack_w<<<(int)((size_t)N_OUT * K_IN / 1024), 256>>>(W, loraB, loraA, scale);

    cudaFuncSetAttribute(lora_mma_gemm,
                         cudaFuncAttributeMaxDynamicSharedMemorySize, SMEM_TOTAL);
    lora_mma_gemm<<<GRID_M * GRID_N, NTHREADS, SMEM_TOTAL>>>(bias, out);
}

// round 10
// speedup vs baseline: 3.5482x; 1.3416x over previous
#include <cuda_runtime.h>
#include <cuda_fp16.h>
#include <cstdint>

#define M_TOK 8192
#define N_OUT 4096
#define K_IN  4096
#define K2    (2 * K_IN)          // A planes: [x1 | x2]; B single plane w1

#define BM 128
#define BN 128
#define BK 64
#define NCHUNK (K_IN / BK)        // 64 (each chunk covers BOTH A planes)
#define NSTAGE 3
#define T_BYTES (128 * BK * 2)    // 16384 per tile
#define STAGE_BYTES (3 * T_BYTES) // A1 + A2 + B = 49152
#define SMEM_TOTAL (NSTAGE * STAGE_BYTES)   // 147456

#define NTHREADS 256

#define GRID_M (M_TOK / BM)       // 64
#define GRID_N (N_OUT / BN)       // 32
#define GROUP_M 8

// -------------------- static device scratch (~168 MB) --------------------
__device__ __half g_ax[(size_t)M_TOK * K2];    // 134 MB  [x1 | x2]
__device__ __half g_bw[(size_t)N_OUT * K_IN];  // 33.5 MB [w1]

// -------------------- helpers --------------------
static __device__ __forceinline__ uint32_t s2u(const void* p) {
    uint32_t a;
    asm("{ .reg .u64 t; cvta.to.shared.u64 t, %1; cvt.u32.u64 %0, t; }"
        : "=r"(a) : "l"(p));
    return a;
}
#define SWZ(o) ((o) ^ (((o) >> 3) & 0x70))

static __device__ __forceinline__ void cp16(uint32_t dst, const void* src) {
    asm volatile("cp.async.cg.shared.global [%0], [%1], 16;" :: "r"(dst), "l"(src));
}
static __device__ __forceinline__ void cp_commit() {
    asm volatile("cp.async.commit_group;" ::: "memory");
}

static __device__ __forceinline__ void ldmx4(uint32_t* r, uint32_t addr) {
    asm volatile("ldmatrix.sync.aligned.m8n8.x4.shared.b16 {%0,%1,%2,%3}, [%4];"
                 : "=r"(r[0]), "=r"(r[1]), "=r"(r[2]), "=r"(r[3]) : "r"(addr));
}
static __device__ __forceinline__ void mma16816(float* c, const uint32_t* a,
                                                uint32_t b0, uint32_t b1) {
    asm volatile(
        "mma.sync.aligned.m16n8k16.row.col.f32.f16.f16.f32 "
        "{%0,%1,%2,%3}, {%4,%5,%6,%7}, {%8,%9}, {%0,%1,%2,%3};"
        : "+f"(c[0]), "+f"(c[1]), "+f"(c[2]), "+f"(c[3])
        : "r"(a[0]), "r"(a[1]), "r"(a[2]), "r"(a[3]), "r"(b0), "r"(b1));
}

static __device__ __forceinline__ void split_h(float v, unsigned short& h1,
                                               unsigned short& h2) {
    __half a = __float2half_rn(v);
    __half b = __float2half_rn(v - __half2float(a));
    h1 = __half_as_ushort(a);
    h2 = __half_as_ushort(b);
}

// ---------- prepass 1: x -> g_ax rows [x1 | x2] (fp16 exact split) ----------
__global__ __launch_bounds__(256) void pack_x(const float* __restrict__ x) {
    size_t idx4 = (size_t)blockIdx.x * 256 + threadIdx.x;
    int row = (int)(idx4 >> 10);
    int col = (int)(idx4 & 1023) * 4;
    float4 v = *(const float4*)(x + (size_t)row * K_IN + col);
    ushort4 h1, h2;
    split_h(v.x, h1.x, h2.x); split_h(v.y, h1.y, h2.y);
    split_h(v.z, h1.z, h2.z); split_h(v.w, h1.w, h2.w);
    unsigned short* base = (unsigned short*)g_ax + (size_t)row * K2 + col;
    *(ushort4*)(base)        = h1;
    *(ushort4*)(base + K_IN) = h2;
}

// ---------- prepass 2: Wf = W + s*B@A -> g_bw single fp16 plane ----------
__global__ __launch_bounds__(256) void pack_w(
    const float* __restrict__ W, const float* __restrict__ B,
    const float* __restrict__ A, const float* __restrict__ sp)
{
    size_t idx4 = (size_t)blockIdx.x * 256 + threadIdx.x;
    int row = (int)(idx4 >> 10);
    int col = (int)(idx4 & 1023) * 4;
    float s = *sp;

    float4 w = *(const float4*)(W + (size_t)row * K_IN + col);
    float4 acc = make_float4(0.f, 0.f, 0.f, 0.f);
    const float* brow = B + (size_t)row * 16;
    #pragma unroll
    for (int r = 0; r < 16; r++) {
        float b = brow[r];
        float4 a = *(const float4*)(A + (size_t)r * K_IN + col);
        acc.x += b * a.x; acc.y += b * a.y; acc.z += b * a.z; acc.w += b * a.w;
    }
    w.x += s * acc.x; w.y += s * acc.y; w.z += s * acc.z; w.w += s * acc.w;

    ushort4 h;
    h.x = __half_as_ushort(__float2half_rn(w.x));
    h.y = __half_as_ushort(__float2half_rn(w.y));
    h.z = __half_as_ushort(__float2half_rn(w.z));
    h.w = __half_as_ushort(__float2half_rn(w.w));
    *(ushort4*)((unsigned short*)g_bw + (size_t)row * K_IN + col) = h;
}

// -------------------- main GEMM: out = (x1+x2) @ w1^T + bias --------------------
__global__ __launch_bounds__(NTHREADS, 1) void lora_mma_gemm(
    const float* __restrict__ bias, float* __restrict__ out)
{
    extern __shared__ __align__(1024) char smem[];
    const uint32_t sb = s2u(smem);
    const int tid  = threadIdx.x;
    const int lane = tid & 31;
    const int wid  = tid >> 5;
    const int warp_m = wid & 1;       // 2 warps in M -> 64 rows each
    const int warp_n = wid >> 1;      // 4 warps in N -> 32 cols each

    const int bid   = blockIdx.x;
    const int group = bid / (GROUP_M * GRID_N);
    const int inner = bid % (GROUP_M * GRID_N);
    const int bm    = (group * GROUP_M + (inner % GROUP_M)) * BM;
    const int bn    = (inner / GROUP_M) * BN;

    const __half* Ag = g_ax + (size_t)bm * K2;
    const __half* Bg = g_bw + (size_t)bn * K_IN;

    const int lrow = lane & 15;
    const int lkb  = (lane >> 4) * 16;

    float c[4][4][4];
    #pragma unroll
    for (int i = 0; i < 4; i++)
        #pragma unroll
        for (int j = 0; j < 4; j++)
            #pragma unroll
            for (int q = 0; q < 4; q++) c[i][j][q] = 0.f;

    // stage layout: [A1 16K | A2 16K | B 16K]
    auto load_stage = [&](int ch, int st) {
        const uint32_t a1 = sb + st * STAGE_BYTES;
        const uint32_t a2 = a1 + T_BYTES;
        const uint32_t bb = a2 + T_BYTES;
        const int k0 = ch * BK;
        #pragma unroll
        for (int i = 0; i < 4; i++) {       // A1: 1024 granules of 16B
            int G = tid + i * NTHREADS;
            int r = G >> 3, g = G & 7;
            uint32_t so = SWZ((uint32_t)(r * 128 + g * 16));
            cp16(a1 + so, Ag + (size_t)r * K2 + k0 + g * 8);
            cp16(a2 + so, Ag + (size_t)r * K2 + K_IN + k0 + g * 8);
            cp16(bb + so, Bg + (size_t)r * K_IN + k0 + g * 8);
        }
        cp_commit();
    };

    #pragma unroll
    for (int s = 0; s < NSTAGE - 1; s++) load_stage(s, s);

    for (int ch = 0; ch < NCHUNK; ch++) {
        asm volatile("cp.async.wait_group 1;" ::: "memory");
        __syncthreads();

        // load stage ch+2 into slot (ch+2)%3 — consumed in iter ch-1, pre-barrier
        if (ch + NSTAGE - 1 < NCHUNK) {
            const int nc = ch + NSTAGE - 1;
            load_stage(nc, nc % NSTAGE);
        } else cp_commit();   // keep group accounting balanced

        const int st = ch % NSTAGE;
        const uint32_t a1 = sb + st * STAGE_BYTES;
        const uint32_t a2 = a1 + T_BYTES;
        const uint32_t bb = a2 + T_BYTES;

        #pragma unroll
        for (int ks = 0; ks < 4; ks++) {
            uint32_t ra1[4][4], ra2[4][4], rb[2][4];
            #pragma unroll
            for (int mf = 0; mf < 4; mf++) {
                uint32_t so = SWZ((uint32_t)((warp_m * 64 + mf * 16 + lrow) * 128
                                             + ks * 32 + lkb));
                ldmx4(ra1[mf], a1 + so);
                ldmx4(ra2[mf], a2 + so);
            }
            #pragma unroll
            for (int nf2 = 0; nf2 < 2; nf2++)
                ldmx4(rb[nf2], bb + SWZ((uint32_t)((warp_n * 32 + nf2 * 16 + lrow) * 128
                                                   + ks * 32 + lkb)));
            #pragma unroll
            for (int mf = 0; mf < 4; mf++)
                #pragma unroll
                for (int nf = 0; nf < 4; nf++) {
                    mma16816(c[mf][nf], ra1[mf],
                             rb[nf >> 1][nf & 1], rb[nf >> 1][(nf & 1) + 2]);
                    mma16816(c[mf][nf], ra2[mf],
                             rb[nf >> 1][nf & 1], rb[nf >> 1][(nf & 1) + 2]);
                }
        }
    }

    // -------- epilogue: regs + bias -> gmem --------
    const int tq = lane >> 2, t4 = lane & 3;
    float2 bv[4];
    #pragma unroll
    for (int nf = 0; nf < 4; nf++)
        bv[nf] = *(const float2*)(bias + bn + warp_n * 32 + nf * 8 + t4 * 2);

    #pragma unroll
    for (int mf = 0; mf < 4; mf++) {
        const int r0 = bm + warp_m * 64 + mf * 16 + tq;
        float* o0 = out + (size_t)r0 * N_OUT + bn + warp_n * 32;
        float* o1 = o0 + 8 * N_OUT;
        #pragma unroll
        for (int nf = 0; nf < 4; nf++) {
            const int colo = nf * 8 + t4 * 2;
            *(float2*)(o0 + colo) = make_float2(c[mf][nf][0] + bv[nf].x,
                                                c[mf][nf][1] + bv[nf].y);
            *(float2*)(o1 + colo) = make_float2(c[mf][nf][2] + bv[nf].x,
                                                c[mf][nf][3] + bv[nf].y);
        }
    }
}

// -------------------- launch --------------------
extern "C" void kernel_launch(void* const* d_in, const int* in_sizes, int n_in,
                              void* d_out, int out_size)
{
    (void)in_sizes; (void)n_in; (void)out_size;
    const float* x     = (const float*)d_in[0];
    const float* W     = (const float*)d_in[1];
    const float* bias  = (const float*)d_in[2];
    const float* loraB = (const float*)d_in[3];
    const float* loraA = (const float*)d_in[4];
    const float* scale = (const float*)d_in[5];
    float* out = (float*)d_out;

    pack_x<<<(int)((size_t)M_TOK * K_IN / 1024), 256>>>(x);
    pack_w<<<(int)((size_t)N_OUT * K_IN / 1024), 256>>>(W, loraB, loraA, scale);

    cudaFuncSetAttribute(lora_mma_gemm,
                         cudaFuncAttributeMaxDynamicSharedMemorySize, SMEM_TOTAL);
    lora_mma_gemm<<<GRID_M * GRID_N, NTHREADS, SMEM_TOTAL>>>(bias, out);
}

// round 11
// speedup vs baseline: 7.5470x; 2.1270x over previous
#include <cuda_runtime.h>
#include <cuda_fp16.h>
#include <cstdint>

#define M_TOK 8192
#define N_OUT 4096
#define K_IN  4096

#define BM 128
#define BN 128
#define BK 64
#define NCHUNK (K_IN / BK)        // 64
#define NSTAGE 3
#define T_BYTES (128 * BK * 2)    // 16384 per tile
#define STAGE_BYTES (2 * T_BYTES) // A + B = 32768
#define SMEM_TOTAL (NSTAGE * STAGE_BYTES)   // 98304 -> 2 CTAs/SM

#define NTHREADS 256

#define GRID_M (M_TOK / BM)       // 64
#define GRID_N (N_OUT / BN)       // 32
#define GROUP_M 8

// -------------------- static device scratch (~100 MB) --------------------
__device__ __half g_ax[(size_t)M_TOK * K_IN];  // 67 MB  fp16(x)
__device__ __half g_bw[(size_t)N_OUT * K_IN];  // 33.5 MB fp16(W + s*B@A)

// -------------------- helpers --------------------
static __device__ __forceinline__ uint32_t s2u(const void* p) {
    uint32_t a;
    asm("{ .reg .u64 t; cvta.to.shared.u64 t, %1; cvt.u32.u64 %0, t; }"
        : "=r"(a) : "l"(p));
    return a;
}
#define SWZ(o) ((o) ^ (((o) >> 3) & 0x70))

static __device__ __forceinline__ void cp16(uint32_t dst, const void* src) {
    asm volatile("cp.async.cg.shared.global [%0], [%1], 16;" :: "r"(dst), "l"(src));
}
static __device__ __forceinline__ void cp_commit() {
    asm volatile("cp.async.commit_group;" ::: "memory");
}

static __device__ __forceinline__ void ldmx4(uint32_t* r, uint32_t addr) {
    asm volatile("ldmatrix.sync.aligned.m8n8.x4.shared.b16 {%0,%1,%2,%3}, [%4];"
                 : "=r"(r[0]), "=r"(r[1]), "=r"(r[2]), "=r"(r[3]) : "r"(addr));
}
static __device__ __forceinline__ void mma16816(float* c, const uint32_t* a,
                                                uint32_t b0, uint32_t b1) {
    asm volatile(
        "mma.sync.aligned.m16n8k16.row.col.f32.f16.f16.f32 "
        "{%0,%1,%2,%3}, {%4,%5,%6,%7}, {%8,%9}, {%0,%1,%2,%3};"
        : "+f"(c[0]), "+f"(c[1]), "+f"(c[2]), "+f"(c[3])
        : "r"(a[0]), "r"(a[1]), "r"(a[2]), "r"(a[3]), "r"(b0), "r"(b1));
}

// ---------- prepass 1: x -> g_ax (single fp16 plane) ----------
__global__ __launch_bounds__(256) void pack_x(const float* __restrict__ x) {
    size_t idx4 = (size_t)blockIdx.x * 256 + threadIdx.x;
    size_t i = idx4 * 4;
    float4 v = *(const float4*)(x + i);
    ushort4 h;
    h.x = __half_as_ushort(__float2half_rn(v.x));
    h.y = __half_as_ushort(__float2half_rn(v.y));
    h.z = __half_as_ushort(__float2half_rn(v.z));
    h.w = __half_as_ushort(__float2half_rn(v.w));
    *(ushort4*)((unsigned short*)g_ax + i) = h;
}

// ---------- prepass 2: Wf = W + s*B@A -> g_bw single fp16 plane ----------
__global__ __launch_bounds__(256) void pack_w(
    const float* __restrict__ W, const float* __restrict__ B,
    const float* __restrict__ A, const float* __restrict__ sp)
{
    size_t idx4 = (size_t)blockIdx.x * 256 + threadIdx.x;
    int row = (int)(idx4 >> 10);
    int col = (int)(idx4 & 1023) * 4;
    float s = *sp;

    float4 w = *(const float4*)(W + (size_t)row * K_IN + col);
    float4 acc = make_float4(0.f, 0.f, 0.f, 0.f);
    const float* brow = B + (size_t)row * 16;
    #pragma unroll
    for (int r = 0; r < 16; r++) {
        float b = brow[r];
        float4 a = *(const float4*)(A + (size_t)r * K_IN + col);
        acc.x += b * a.x; acc.y += b * a.y; acc.z += b * a.z; acc.w += b * a.w;
    }
    w.x += s * acc.x; w.y += s * acc.y; w.z += s * acc.z; w.w += s * acc.w;

    ushort4 h;
    h.x = __half_as_ushort(__float2half_rn(w.x));
    h.y = __half_as_ushort(__float2half_rn(w.y));
    h.z = __half_as_ushort(__float2half_rn(w.z));
    h.w = __half_as_ushort(__float2half_rn(w.w));
    *(ushort4*)((unsigned short*)g_bw + (size_t)row * K_IN + col) = h;
}

// -------------------- main GEMM: out = x_h @ w_h^T + bias --------------------
__global__ __launch_bounds__(NTHREADS, 2) void lora_mma_gemm(
    const float* __restrict__ bias, float* __restrict__ out)
{
    extern __shared__ __align__(1024) char smem[];
    const uint32_t sb = s2u(smem);
    const int tid  = threadIdx.x;
    const int lane = tid & 31;
    const int wid  = tid >> 5;
    const int warp_m = wid & 1;       // 2 warps in M -> 64 rows each
    const int warp_n = wid >> 1;      // 4 warps in N -> 32 cols each

    const int bid   = blockIdx.x;
    const int group = bid / (GROUP_M * GRID_N);
    const int inner = bid % (GROUP_M * GRID_N);
    const int bm    = (group * GROUP_M + (inner % GROUP_M)) * BM;
    const int bn    = (inner / GROUP_M) * BN;

    const __half* Ag = g_ax + (size_t)bm * K_IN;
    const __half* Bg = g_bw + (size_t)bn * K_IN;

    const int lrow = lane & 15;
    const int lkb  = (lane >> 4) * 16;

    float c[4][4][4];
    #pragma unroll
    for (int i = 0; i < 4; i++)
        #pragma unroll
        for (int j = 0; j < 4; j++)
            #pragma unroll
            for (int q = 0; q < 4; q++) c[i][j][q] = 0.f;

    // stage layout: [A 16K | B 16K]
    auto load_stage = [&](int ch, int st) {
        const uint32_t ab = sb + st * STAGE_BYTES;
        const uint32_t bb = ab + T_BYTES;
        const int k0 = ch * BK;
        #pragma unroll
        for (int i = 0; i < 4; i++) {       // 1024 granules of 16B per tile
            int G = tid + i * NTHREADS;
            int r = G >> 3, g = G & 7;
            uint32_t so = SWZ((uint32_t)(r * 128 + g * 16));
            cp16(ab + so, Ag + (size_t)r * K_IN + k0 + g * 8);
            cp16(bb + so, Bg + (size_t)r * K_IN + k0 + g * 8);
        }
        cp_commit();
    };

    #pragma unroll
    for (int s = 0; s < NSTAGE - 1; s++) load_stage(s, s);

    for (int ch = 0; ch < NCHUNK; ch++) {
        asm volatile("cp.async.wait_group 1;" ::: "memory");
        __syncthreads();

        // load stage ch+2 into slot (ch+2)%3 — consumed in iter ch-1, pre-barrier
        if (ch + NSTAGE - 1 < NCHUNK) {
            const int nc = ch + NSTAGE - 1;
            load_stage(nc, nc % NSTAGE);
        } else cp_commit();   // keep group accounting balanced

        const int st = ch % NSTAGE;
        const uint32_t ab = sb + st * STAGE_BYTES;
        const uint32_t bb = ab + T_BYTES;

        #pragma unroll
        for (int ks = 0; ks < 4; ks++) {
            uint32_t ra[4][4], rb[2][4];
            #pragma unroll
            for (int mf = 0; mf < 4; mf++)
                ldmx4(ra[mf], ab + SWZ((uint32_t)((warp_m * 64 + mf * 16 + lrow) * 128
                                                  + ks * 32 + lkb)));
            #pragma unroll
            for (int nf2 = 0; nf2 < 2; nf2++)
                ldmx4(rb[nf2], bb + SWZ((uint32_t)((warp_n * 32 + nf2 * 16 + lrow) * 128
                                                   + ks * 32 + lkb)));
            #pragma unroll
            for (int mf = 0; mf < 4; mf++)
                #pragma unroll
                for (int nf = 0; nf < 4; nf++)
                    mma16816(c[mf][nf], ra[mf],
                             rb[nf >> 1][nf & 1], rb[nf >> 1][(nf & 1) + 2]);
        }
    }

    // -------- epilogue: regs + bias -> gmem --------
    const int tq = lane >> 2, t4 = lane & 3;
    float2 bv[4];
    #pragma unroll
    for (int nf = 0; nf < 4; nf++)
        bv[nf] = *(const float2*)(bias + bn + warp_n * 32 + nf * 8 + t4 * 2);

    #pragma unroll
    for (int mf = 0; mf < 4; mf++) {
        const int r0 = bm + warp_m * 64 + mf * 16 + tq;
        float* o0 = out + (size_t)r0 * N_OUT + bn + warp_n * 32;
        float* o1 = o0 + 8 * N_OUT;
        #pragma unroll
        for (int nf = 0; nf < 4; nf++) {
            const int colo = nf * 8 + t4 * 2;
            *(float2*)(o0 + colo) = make_float2(c[mf][nf][0] + bv[nf].x,
                                                c[mf][nf][1] + bv[nf].y);
            *(float2*)(o1 + colo) = make_float2(c[mf][nf][2] + bv[nf].x,
                                                c[mf][nf][3] + bv[nf].y);
        }
    }
}

// -------------------- launch --------------------
extern "C" void kernel_launch(void* const* d_in, const int* in_sizes, int n_in,
                              void* d_out, int out_size)
{
    (void)in_sizes; (void)n_in; (void)out_size;
    const float* x     = (const float*)d_in[0];
    const float* W     = (const float*)d_in[1];
    const float* bias  = (const float*)d_in[2];
    const float* loraB = (const float*)d_in[3];
    const float* loraA = (const float*)d_in[4];
    const float* scale = (const float*)d_in[5];
    float* out = (float*)d_out;

    pack_x<<<(int)((size_t)M_TOK * K_IN / 1024), 256>>>(x);
    pack_w<<<(int)((size_t)N_OUT * K_IN / 1024), 256>>>(W, loraB, loraA, scale);

    cudaFuncSetAttribute(lora_mma_gemm,
                         cudaFuncAttributeMaxDynamicSharedMemorySize, SMEM_TOTAL);
    lora_mma_gemm<<<GRID_M * GRID_N, NTHREADS, SMEM_TOTAL>>>(bias, out);
}